// round 15
// baseline (speedup 1.0000x reference)
#include <cuda_runtime.h>
#include <cuda_fp16.h>
#include <cstdint>

// ---------------------------------------------------------------------------
// Problem constants
// ---------------------------------------------------------------------------
namespace {
constexpr int kHeads = 12;
constexpr int kTok   = 197;               // N_PATCH + 1
constexpr int kDim   = 768;
constexpr int kBatch = 64;
constexpr int kM     = kBatch * kTok;     // 12608
constexpr int kQkvN  = 3 * kDim;          // 2304
constexpr float kScale = 0.125f;          // hd^-0.5
}  // namespace

// Scratch (static device globals; no runtime allocation allowed)
__device__ __half g_qkv[(size_t)kM * kQkvN];            // (B, N, 3C) fp16
__device__ __half g_attn[(size_t)kM * kDim];            // (B, N, C) fp16
__device__ float  g_rpb[(size_t)kHeads * kTok * kTok];  // (H, N, N) fp32
__device__ __half g_x[(size_t)kM * kDim];               // fp16 x
__device__ __half g_wqkv[(size_t)kQkvN * kDim];         // fp16 qkv_w
__device__ __half g_wproj[(size_t)kDim * kDim];         // fp16 proj_w

// ---------------------------------------------------------------------------
// Elementwise fp32 -> fp16 conversion (n divisible by 4)
// ---------------------------------------------------------------------------
__global__ void f2h_kernel(const float* __restrict__ in, __half* __restrict__ out,
                           int n4) {
  int i = blockIdx.x * blockDim.x + threadIdx.x;
  if (i >= n4) return;
  float4 v = ((const float4*)in)[i];
  __half2 h0 = __floats2half2_rn(v.x, v.y);
  __half2 h1 = __floats2half2_rn(v.z, v.w);
  ((__half2*)out)[i * 2 + 0] = h0;
  ((__half2*)out)[i * 2 + 1] = h1;
}

// ---------------------------------------------------------------------------
// Relative position bias expansion: g_rpb[h][i][j] = table[idx[i][j]][h]
// ---------------------------------------------------------------------------
__global__ void rpb_expand(const int* __restrict__ idx, const float* __restrict__ tbl) {
  int t = blockIdx.x * blockDim.x + threadIdx.x;
  if (t >= kTok * kTok) return;
  int id = idx[t];
#pragma unroll
  for (int h = 0; h < kHeads; h++)
    g_rpb[(size_t)h * kTok * kTok + t] = tbl[id * kHeads + h];
}

// ---------------------------------------------------------------------------
// mma / ldmatrix helpers
// ---------------------------------------------------------------------------
__device__ __forceinline__ void mma_f16(float (&d)[4], const uint32_t* a,
                                        const uint32_t* b) {
  asm volatile(
      "mma.sync.aligned.m16n8k16.row.col.f32.f16.f16.f32 "
      "{%0,%1,%2,%3}, {%4,%5,%6,%7}, {%8,%9}, {%0,%1,%2,%3};"
      : "+f"(d[0]), "+f"(d[1]), "+f"(d[2]), "+f"(d[3])
      : "r"(a[0]), "r"(a[1]), "r"(a[2]), "r"(a[3]), "r"(b[0]), "r"(b[1]));
}

__device__ __forceinline__ void ldm_x4(uint32_t (&r)[4], uint32_t addr) {
  asm volatile("ldmatrix.sync.aligned.m8n8.x4.shared.b16 {%0,%1,%2,%3}, [%4];"
               : "=r"(r[0]), "=r"(r[1]), "=r"(r[2]), "=r"(r[3]) : "r"(addr));
}

__device__ __forceinline__ void ldm_x4_t(uint32_t (&r)[4], uint32_t addr) {
  asm volatile("ldmatrix.sync.aligned.m8n8.x4.trans.shared.b16 {%0,%1,%2,%3}, [%4];"
               : "=r"(r[0]), "=r"(r[1]), "=r"(r[2]), "=r"(r[3]) : "r"(addr));
}

__device__ __forceinline__ void cp_async16(uint32_t dst, const void* src, bool pred) {
  int sz = pred ? 16 : 0;
  asm volatile("cp.async.ca.shared.global [%0], [%1], 16, %2;"
               :: "r"(dst), "l"(src), "r"(sz));
}
__device__ __forceinline__ void cp_commit() { asm volatile("cp.async.commit_group;"); }
__device__ __forceinline__ void cp_wait0()  { asm volatile("cp.async.wait_group 0;"); }
__device__ __forceinline__ void cp_wait1()  { asm volatile("cp.async.wait_group 1;"); }

// ---------------------------------------------------------------------------
// FP16 tensor-core GEMM (unchanged from R13 — proven 413us config).
// Block tile 128x128x64(half), 3-stage cp.async, warp tile 64x32, 2 CTAs/SM.
// ---------------------------------------------------------------------------
namespace {
constexpr int kStages       = 3;
constexpr int kSmStrideH    = 72;                        // halfs per row
constexpr int kHalfBytes    = 128 * kSmStrideH * 2;      // 18432 (A or B)
constexpr int kStageBytes   = 2 * kHalfBytes;            // 36864
constexpr int kGemmSmemBytes = kStages * kStageBytes;    // 110592
}  // namespace

template <int MODE>
__global__ __launch_bounds__(256, 2)
void gemm_f16(const __half* __restrict__ A, const __half* __restrict__ W,
              void* __restrict__ Cv, int M, int K, int N,
              const float* __restrict__ b0, const float* __restrict__ b1) {
  extern __shared__ __align__(16) unsigned char smraw[];

  const int t    = threadIdx.x;
  const int lane = t & 31;
  const int wid  = t >> 5;
  const int wm   = (wid >> 2) * 64;   // 0 or 64
  const int wn   = (wid & 3) * 32;    // 0,32,64,96
  const int m0   = blockIdx.y * 128;
  const int n0   = blockIdx.x * 128;

  const uint32_t sb = (uint32_t)__cvta_generic_to_shared(smraw);

  auto issue_stage = [&](int c) {
    uint32_t base = sb + (uint32_t)(c % 3) * kStageBytes;
    int k0 = c * 64;
#pragma unroll
    for (int i = 0; i < 4; i++) {
      int idx = t + i * 256;
      int row = idx >> 3;          // 0..127
      int j   = idx & 7;           // 16B chunk (8 halfs)
      uint32_t off = (uint32_t)(row * kSmStrideH * 2 + j * 16);
      int mg = m0 + row;
      cp_async16(base + off, A + (size_t)mg * K + k0 + j * 8, mg < M);
      cp_async16(base + kHalfBytes + off, W + (size_t)(n0 + row) * K + k0 + j * 8,
                 true);
    }
  };

  const int nkb = K / 64;   // 12
#pragma unroll
  for (int s = 0; s < kStages - 1; s++) { issue_stage(s); cp_commit(); }

  float acc[4][4][4] = {};

  const int l7    = lane & 7;
  const int a_row = wm + l7 + ((lane >> 3) & 1) * 8;   // + mt*16
  const int a_col = ((lane >> 4) & 1) * 8;             // + ks*16
  const int b_row = wn + ((lane >> 4) & 1) * 8 + l7;   // + pair*16
  const int b_col = ((lane >> 3) & 1) * 8;             // + ks*16

  for (int kb = 0; kb < nkb; kb++) {
    cp_wait1();
    __syncthreads();
    if (kb + kStages - 1 < nkb) issue_stage(kb + kStages - 1);
    cp_commit();

    const uint32_t Ab = sb + (uint32_t)(kb % 3) * kStageBytes;
    const uint32_t Bb = Ab + kHalfBytes;

#pragma unroll
    for (int ks = 0; ks < 4; ks++) {
      uint32_t af[4][4], bf[2][4];
#pragma unroll
      for (int mt = 0; mt < 4; mt++)
        ldm_x4(af[mt], Ab + (uint32_t)(((a_row + mt * 16) * kSmStrideH +
                                        ks * 16 + a_col) * 2));
#pragma unroll
      for (int p = 0; p < 2; p++)
        ldm_x4(bf[p], Bb + (uint32_t)(((b_row + p * 16) * kSmStrideH +
                                       ks * 16 + b_col) * 2));
#pragma unroll
      for (int mt = 0; mt < 4; mt++)
#pragma unroll
        for (int nt = 0; nt < 4; nt++)
          mma_f16(acc[mt][nt], af[mt], &bf[nt >> 1][(nt & 1) * 2]);
    }
  }

  // ---- epilogue ----
  const int mrow = lane >> 2;
  const int ncol = (lane & 3) * 2;
#pragma unroll
  for (int mt = 0; mt < 4; mt++) {
#pragma unroll
    for (int half_ = 0; half_ < 2; half_++) {
      int m = m0 + wm + mt * 16 + mrow + half_ * 8;
      if (m >= M) continue;
#pragma unroll
      for (int nt = 0; nt < 4; nt++) {
        int n = n0 + wn + nt * 8 + ncol;
        float v0 = acc[mt][nt][half_ * 2 + 0];
        float v1 = acc[mt][nt][half_ * 2 + 1];
        if (MODE == 0) {
          float bias0 = (n < kDim) ? b0[n] : ((n < 2 * kDim) ? 0.f : b1[n - 2 * kDim]);
          float bias1 = (n + 1 < kDim) ? b0[n + 1]
                        : ((n + 1 < 2 * kDim) ? 0.f : b1[n + 1 - 2 * kDim]);
          v0 += bias0; v1 += bias1;
          if (n < kDim) { v0 *= kScale; v1 *= kScale; }
          __half* C = (__half*)Cv;
          *(__half2*)(C + (size_t)m * N + n) = __floats2half2_rn(v0, v1);
        } else {
          float* C = (float*)Cv;
          v0 += b0[n]; v1 += b0[n + 1];
          *(float2*)(C + (size_t)m * N + n) = make_float2(v0, v1);
        }
      }
    }
  }
}

// ---------------------------------------------------------------------------
// FP16 tensor-core attention with cp.async K/V pipeline.
// One block = (b,h) x 32 query rows, 8 warps, 2 CTAs/SM.
// K and V both stored row-major [row][64] stride 72 halfs in 2 ping-pong
// buffers. Groups: K0,K1,V0,V1; waits 1/1/1/0 with barriers. V's B-operand
// for P@V comes via ldmatrix.x4.trans (no scalar transpose).
// ---------------------------------------------------------------------------
namespace {
constexpr int TQ    = 32;
constexpr int KC    = 128;
constexpr int SSTR  = 260;   // S (float) row stride
constexpr int QSTRH = 72;
constexpr int PSTRH = 264;
constexpr int KVSTR = 72;    // K/V row stride (halfs)
constexpr int kOffQs = TQ * SSTR * 4;                 // 33280
constexpr int kOffPh = kOffQs + TQ * QSTRH * 2;       // 37888
constexpr int kOffKV = kOffPh + TQ * PSTRH * 2;       // 54784
constexpr int kKVBuf = KC * KVSTR * 2;                // 18432 per buffer
constexpr int kAttnSmemBytes = kOffKV + 2 * kKVBuf;   // 91648
}  // namespace

__global__ __launch_bounds__(256, 2)
void attn_kernel() {
  extern __shared__ __align__(16) unsigned char smraw[];
  float*  S  = (float*)smraw;
  __half* Qs = (__half*)(smraw + kOffQs);
  __half* Ph = (__half*)(smraw + kOffPh);

  const int t    = threadIdx.x;
  const int lane = t & 31;
  const int w    = t >> 5;
  const int tile = blockIdx.x;
  const int bh   = blockIdx.y;
  const int b    = bh / kHeads;
  const int h    = bh - b * kHeads;
  const int i0g  = tile * TQ;

  const __half* Qb = g_qkv + (size_t)b * kTok * kQkvN + h * 64;
  const __half* Kb = Qb + kDim;
  const __half* Vb = Qb + 2 * kDim;

  const uint32_t uQs  = (uint32_t)__cvta_generic_to_shared(Qs);
  const uint32_t uPh  = (uint32_t)__cvta_generic_to_shared(Ph);
  const uint32_t uKV0 = (uint32_t)__cvta_generic_to_shared(smraw + kOffKV);
  const uint32_t uKV1 = uKV0 + kKVBuf;

  const int l7   = lane & 7;
  const int mrow = (w & 1) * 16;
  const int a_row = mrow + l7 + ((lane >> 3) & 1) * 8;
  const int a_col = ((lane >> 4) & 1) * 8;
  const int b_rowoff = ((lane >> 4) & 1) * 8 + l7;   // non-trans (K phase)
  const int b_col    = ((lane >> 3) & 1) * 8;
  const int vb_row = ((lane >> 3) & 1) * 8 + l7;     // trans (V phase): k rows
  const int vb_col = ((lane >> 4) & 1) * 8;          // trans: n (d) cols
  const int lm = lane >> 2;
  const int lk = lane & 3;

  // KV chunk loader: 128 rows x 64 halfs via cp.async (zero-fill past kTok)
  auto load_kv = [&](const __half* src, uint32_t dstbase, int c0) {
#pragma unroll
    for (int i = 0; i < 4; i++) {
      int idx = t + i * 256;
      int row = idx >> 3;        // 0..127
      int j   = idx & 7;         // 16B chunk
      int gr  = c0 + row;
      int gc  = (gr < kTok) ? gr : (kTok - 1);   // clamp addr; zfill via pred
      cp_async16(dstbase + (uint32_t)(row * KVSTR * 2 + j * 16),
                 src + (size_t)gc * kQkvN + j * 8, gr < kTok);
    }
    cp_commit();
  };

  // ---- issue K0, K1; stage Q ----
  load_kv(Kb, uKV0, 0);      // group 1
  load_kv(Kb, uKV1, KC);     // group 2
  {
    int i  = t >> 3;
    int d0 = (t & 7) * 8;
    int qi = i0g + i;
    uint4 v = {0u, 0u, 0u, 0u};
    if (qi < kTok) v = *(const uint4*)(Qb + (size_t)qi * kQkvN + d0);
    *(uint4*)&Qs[i * QSTRH + d0] = v;
  }
  __syncthreads();

  uint32_t aq[4][4];
#pragma unroll
  for (int ks = 0; ks < 4; ks++)
    ldm_x4(aq[ks], uQs + (uint32_t)((a_row * QSTRH + ks * 16 + a_col) * 2));

  // ---- Phase A: S = Q @ K^T (2 chunks, prefetched) ----
#pragma unroll
  for (int c0i = 0; c0i < 2; c0i++) {
    const int j0 = c0i * KC;
    const uint32_t uK = c0i ? uKV1 : uKV0;
    cp_wait1();
    __syncthreads();

    float acc[4][4] = {};
#pragma unroll
    for (int ks = 0; ks < 4; ks++) {
      uint32_t bf[2][4];
#pragma unroll
      for (int p = 0; p < 2; p++) {
        int nb = (w >> 1) * 32 + p * 16;
        ldm_x4(bf[p], uK + (uint32_t)(((nb + b_rowoff) * KVSTR +
                                       ks * 16 + b_col) * 2));
      }
#pragma unroll
      for (int nt = 0; nt < 4; nt++)
        mma_f16(acc[nt], aq[ks], &bf[nt >> 1][(nt & 1) * 2]);
    }
#pragma unroll
    for (int nt = 0; nt < 4; nt++) {
      int col = j0 + ((w >> 1) * 4 + nt) * 8 + lk * 2;
      int r   = mrow + lm;
      *(float2*)&S[r * SSTR + col]       = make_float2(acc[nt][0], acc[nt][1]);
      *(float2*)&S[(r + 8) * SSTR + col] = make_float2(acc[nt][2], acc[nt][3]);
    }
    __syncthreads();                 // all warps done with this K buffer
    load_kv(Vb, uK, j0);             // overwrite with V chunk (groups 3, 4)
  }

  // ---- Phase B: softmax(S + rpb) in fp32, write probs fp16 to Ph ----
  // (V0/V1 loads are in flight underneath this)
  {
#pragma unroll
    for (int r = 0; r < 4; r++) {
      int i  = w * 4 + r;
      int qi = min(i0g + i, kTok - 1);
      const float* rp = g_rpb + ((size_t)h * kTok + qi) * kTok;
      float vals[7];
      float mx = -1e30f;
#pragma unroll
      for (int k = 0; k < 7; k++) {
        int j = lane + k * 32;
        float v = -1e30f;
        if (j < kTok) v = S[i * SSTR + j] + rp[j];
        vals[k] = v;
        mx = fmaxf(mx, v);
      }
#pragma unroll
      for (int o = 16; o; o >>= 1) mx = fmaxf(mx, __shfl_xor_sync(0xffffffffu, mx, o));
      float sum = 0.f;
#pragma unroll
      for (int k = 0; k < 7; k++) {
        int j = lane + k * 32;
        float e = (j < kTok) ? __expf(vals[k] - mx) : 0.f;
        vals[k] = e;
        sum += e;
      }
#pragma unroll
      for (int o = 16; o; o >>= 1) sum += __shfl_xor_sync(0xffffffffu, sum, o);
      float inv = 1.f / sum;
#pragma unroll
      for (int k = 0; k < 7; k++) {
        int j = lane + k * 32;
        Ph[i * PSTRH + j] = __float2half_rn((j < kTok) ? vals[k] * inv : 0.f);
      }
      Ph[i * PSTRH + 224 + lane] = __float2half_rn(0.f);
    }
  }

  // ---- Phase C: O = P @ V (V row-major; B-fragment via ldmatrix.trans) ----
  float accO[2][4] = {};
  const int nb = (w >> 1) * 16;   // d base for this warp pair
#pragma unroll
  for (int c0i = 0; c0i < 2; c0i++) {
    const int j0 = c0i * KC;
    const uint32_t uV = c0i ? uKV1 : uKV0;
    if (c0i == 0) cp_wait1(); else cp_wait0();
    __syncthreads();   // Ph visible (c0i==0) + all threads' V parts landed

#pragma unroll
    for (int ks = 0; ks < 8; ks++) {
      uint32_t ap[4], bv[4];
      ldm_x4(ap, uPh + (uint32_t)((a_row * PSTRH + j0 + ks * 16 + a_col) * 2));
      ldm_x4_t(bv, uV + (uint32_t)(((ks * 16 + vb_row) * KVSTR +
                                    nb + vb_col) * 2));
#pragma unroll
      for (int nt = 0; nt < 2; nt++)
        mma_f16(accO[nt], ap, &bv[nt * 2]);
    }
  }

  // ---- epilogue: write g_attn (fp16) ----
#pragma unroll
  for (int nt = 0; nt < 2; nt++) {
    int dcol = nb + nt * 8 + lk * 2;
#pragma unroll
    for (int half_ = 0; half_ < 2; half_++) {
      int i = i0g + mrow + lm + half_ * 8;
      if (i < kTok) {
        __half2 hv = __floats2half2_rn(accO[nt][half_ * 2 + 0],
                                       accO[nt][half_ * 2 + 1]);
        *(__half2*)(g_attn + ((size_t)b * kTok + i) * kDim + h * 64 + dcol) = hv;
      }
    }
  }
}

// ---------------------------------------------------------------------------
// Launch
// ---------------------------------------------------------------------------
extern "C" void kernel_launch(void* const* d_in, const int* in_sizes, int n_in,
                              void* d_out, int out_size) {
  const float* x         = (const float*)d_in[0];
  const float* qkv_w     = (const float*)d_in[1];
  const float* q_bias    = (const float*)d_in[2];
  const float* v_bias    = (const float*)d_in[3];
  const float* rpb_table = (const float*)d_in[4];
  const float* proj_w    = (const float*)d_in[5];
  const float* proj_b    = (const float*)d_in[6];
  const int*   rel_idx   = (const int*)d_in[7];
  float* out = (float*)d_out;

  __half *qkv_ptr, *attn_ptr, *x_ptr, *wqkv_ptr, *wproj_ptr;
  cudaGetSymbolAddress((void**)&qkv_ptr, g_qkv);
  cudaGetSymbolAddress((void**)&attn_ptr, g_attn);
  cudaGetSymbolAddress((void**)&x_ptr, g_x);
  cudaGetSymbolAddress((void**)&wqkv_ptr, g_wqkv);
  cudaGetSymbolAddress((void**)&wproj_ptr, g_wproj);

  // (0) fp32 -> fp16 conversion of GEMM inputs
  {
    int n4 = kM * kDim / 4;
    f2h_kernel<<<(n4 + 255) / 256, 256>>>(x, x_ptr, n4);
    n4 = kQkvN * kDim / 4;
    f2h_kernel<<<(n4 + 255) / 256, 256>>>(qkv_w, wqkv_ptr, n4);
    n4 = kDim * kDim / 4;
    f2h_kernel<<<(n4 + 255) / 256, 256>>>(proj_w, wproj_ptr, n4);
  }

  // (1) relative position bias expansion
  rpb_expand<<<(kTok * kTok + 255) / 256, 256>>>(rel_idx, rpb_table);

  // (2) QKV projection (fp16 in, fp16 out with bias + q-scale)
  cudaFuncSetAttribute(gemm_f16<0>, cudaFuncAttributeMaxDynamicSharedMemorySize,
                       kGemmSmemBytes);
  {
    dim3 grid(kQkvN / 128, (kM + 127) / 128);
    gemm_f16<0><<<grid, 256, kGemmSmemBytes>>>(x_ptr, wqkv_ptr, qkv_ptr,
                                               kM, kDim, kQkvN, q_bias, v_bias);
  }

  // (3) fp16 tensor-core attention (pipelined K/V)
  cudaFuncSetAttribute(attn_kernel, cudaFuncAttributeMaxDynamicSharedMemorySize,
                       kAttnSmemBytes);
  attn_kernel<<<dim3(7, kBatch * kHeads), 256, kAttnSmemBytes>>>();

  // (4) output projection (fp16 in, fp32 out with bias)
  cudaFuncSetAttribute(gemm_f16<1>, cudaFuncAttributeMaxDynamicSharedMemorySize,
                       kGemmSmemBytes);
  {
    dim3 grid(kDim / 128, (kM + 127) / 128);
    gemm_f16<1><<<grid, 256, kGemmSmemBytes>>>(attn_ptr, wproj_ptr, out,
                                               kM, kDim, kDim, proj_b, nullptr);
  }
}

// round 16
// speedup vs baseline: 1.0072x; 1.0072x over previous
#include <cuda_runtime.h>
#include <cuda_fp16.h>
#include <cstdint>

// ---------------------------------------------------------------------------
// Problem constants
// ---------------------------------------------------------------------------
namespace {
constexpr int kHeads = 12;
constexpr int kTok   = 197;               // N_PATCH + 1
constexpr int kDim   = 768;
constexpr int kBatch = 64;
constexpr int kM     = kBatch * kTok;     // 12608
constexpr int kQkvN  = 3 * kDim;          // 2304
constexpr float kScale = 0.125f;          // hd^-0.5
}  // namespace

// Scratch (static device globals; no runtime allocation allowed)
__device__ __half g_qkv[(size_t)kM * kQkvN];            // (B, N, 3C) fp16
__device__ __half g_attn[(size_t)kM * kDim];            // (B, N, C) fp16
__device__ float  g_rpb[(size_t)kHeads * kTok * kTok];  // (H, N, N) fp32
__device__ __half g_x[(size_t)kM * kDim];               // fp16 x
__device__ __half g_wqkv[(size_t)kQkvN * kDim];         // fp16 qkv_w
__device__ __half g_wproj[(size_t)kDim * kDim];         // fp16 proj_w

// ---------------------------------------------------------------------------
// Fused fp32 -> fp16 conversion of x, qkv_w, proj_w (single launch)
// ---------------------------------------------------------------------------
namespace {
constexpr int kN4X = kM * kDim / 4;       // 2420736
constexpr int kN4W = kQkvN * kDim / 4;    // 442368
constexpr int kN4P = kDim * kDim / 4;     // 147456
constexpr int kN4Total = kN4X + kN4W + kN4P;
}  // namespace

__global__ void f2h_fused(const float* __restrict__ x, const float* __restrict__ wq,
                          const float* __restrict__ wp) {
  int i = blockIdx.x * blockDim.x + threadIdx.x;
  if (i >= kN4Total) return;
  const float* src;
  __half* dst;
  int off;
  if (i < kN4X) {
    src = x; dst = g_x; off = i;
  } else if (i < kN4X + kN4W) {
    src = wq; dst = g_wqkv; off = i - kN4X;
  } else {
    src = wp; dst = g_wproj; off = i - kN4X - kN4W;
  }
  float4 v = ((const float4*)src)[off];
  ((__half2*)dst)[off * 2 + 0] = __floats2half2_rn(v.x, v.y);
  ((__half2*)dst)[off * 2 + 1] = __floats2half2_rn(v.z, v.w);
}

// ---------------------------------------------------------------------------
// Relative position bias expansion: g_rpb[h][i][j] = table[idx[i][j]][h]
// ---------------------------------------------------------------------------
__global__ void rpb_expand(const int* __restrict__ idx, const float* __restrict__ tbl) {
  int t = blockIdx.x * blockDim.x + threadIdx.x;
  if (t >= kTok * kTok) return;
  int id = idx[t];
#pragma unroll
  for (int h = 0; h < kHeads; h++)
    g_rpb[(size_t)h * kTok * kTok + t] = tbl[id * kHeads + h];
}

// ---------------------------------------------------------------------------
// mma / ldmatrix helpers
// ---------------------------------------------------------------------------
__device__ __forceinline__ void mma_f16(float (&d)[4], const uint32_t* a,
                                        const uint32_t* b) {
  asm volatile(
      "mma.sync.aligned.m16n8k16.row.col.f32.f16.f16.f32 "
      "{%0,%1,%2,%3}, {%4,%5,%6,%7}, {%8,%9}, {%0,%1,%2,%3};"
      : "+f"(d[0]), "+f"(d[1]), "+f"(d[2]), "+f"(d[3])
      : "r"(a[0]), "r"(a[1]), "r"(a[2]), "r"(a[3]), "r"(b[0]), "r"(b[1]));
}

__device__ __forceinline__ void ldm_x4(uint32_t (&r)[4], uint32_t addr) {
  asm volatile("ldmatrix.sync.aligned.m8n8.x4.shared.b16 {%0,%1,%2,%3}, [%4];"
               : "=r"(r[0]), "=r"(r[1]), "=r"(r[2]), "=r"(r[3]) : "r"(addr));
}

__device__ __forceinline__ void ldm_x4_t(uint32_t (&r)[4], uint32_t addr) {
  asm volatile("ldmatrix.sync.aligned.m8n8.x4.trans.shared.b16 {%0,%1,%2,%3}, [%4];"
               : "=r"(r[0]), "=r"(r[1]), "=r"(r[2]), "=r"(r[3]) : "r"(addr));
}

__device__ __forceinline__ void cp_async16(uint32_t dst, const void* src, bool pred) {
  int sz = pred ? 16 : 0;
  asm volatile("cp.async.ca.shared.global [%0], [%1], 16, %2;"
               :: "r"(dst), "l"(src), "r"(sz));
}
__device__ __forceinline__ void cp_commit() { asm volatile("cp.async.commit_group;"); }
__device__ __forceinline__ void cp_wait0()  { asm volatile("cp.async.wait_group 0;"); }
__device__ __forceinline__ void cp_wait1()  { asm volatile("cp.async.wait_group 1;"); }

// ---------------------------------------------------------------------------
// FP16 tensor-core GEMM (unchanged from R13/R15 — proven config).
// Block tile 128x128x64(half), 3-stage cp.async, warp tile 64x32, 2 CTAs/SM.
// ---------------------------------------------------------------------------
namespace {
constexpr int kStages       = 3;
constexpr int kSmStrideH    = 72;                        // halfs per row
constexpr int kHalfBytes    = 128 * kSmStrideH * 2;      // 18432 (A or B)
constexpr int kStageBytes   = 2 * kHalfBytes;            // 36864
constexpr int kGemmSmemBytes = kStages * kStageBytes;    // 110592
}  // namespace

template <int MODE>
__global__ __launch_bounds__(256, 2)
void gemm_f16(const __half* __restrict__ A, const __half* __restrict__ W,
              void* __restrict__ Cv, int M, int K, int N,
              const float* __restrict__ b0, const float* __restrict__ b1) {
  extern __shared__ __align__(16) unsigned char smraw[];

  const int t    = threadIdx.x;
  const int lane = t & 31;
  const int wid  = t >> 5;
  const int wm   = (wid >> 2) * 64;   // 0 or 64
  const int wn   = (wid & 3) * 32;    // 0,32,64,96
  const int m0   = blockIdx.y * 128;
  const int n0   = blockIdx.x * 128;

  const uint32_t sb = (uint32_t)__cvta_generic_to_shared(smraw);

  auto issue_stage = [&](int c) {
    uint32_t base = sb + (uint32_t)(c % 3) * kStageBytes;
    int k0 = c * 64;
#pragma unroll
    for (int i = 0; i < 4; i++) {
      int idx = t + i * 256;
      int row = idx >> 3;          // 0..127
      int j   = idx & 7;           // 16B chunk (8 halfs)
      uint32_t off = (uint32_t)(row * kSmStrideH * 2 + j * 16);
      int mg = m0 + row;
      cp_async16(base + off, A + (size_t)mg * K + k0 + j * 8, mg < M);
      cp_async16(base + kHalfBytes + off, W + (size_t)(n0 + row) * K + k0 + j * 8,
                 true);
    }
  };

  const int nkb = K / 64;   // 12
#pragma unroll
  for (int s = 0; s < kStages - 1; s++) { issue_stage(s); cp_commit(); }

  float acc[4][4][4] = {};

  const int l7    = lane & 7;
  const int a_row = wm + l7 + ((lane >> 3) & 1) * 8;   // + mt*16
  const int a_col = ((lane >> 4) & 1) * 8;             // + ks*16
  const int b_row = wn + ((lane >> 4) & 1) * 8 + l7;   // + pair*16
  const int b_col = ((lane >> 3) & 1) * 8;             // + ks*16

  for (int kb = 0; kb < nkb; kb++) {
    cp_wait1();
    __syncthreads();
    if (kb + kStages - 1 < nkb) issue_stage(kb + kStages - 1);
    cp_commit();

    const uint32_t Ab = sb + (uint32_t)(kb % 3) * kStageBytes;
    const uint32_t Bb = Ab + kHalfBytes;

#pragma unroll
    for (int ks = 0; ks < 4; ks++) {
      uint32_t af[4][4], bf[2][4];
#pragma unroll
      for (int mt = 0; mt < 4; mt++)
        ldm_x4(af[mt], Ab + (uint32_t)(((a_row + mt * 16) * kSmStrideH +
                                        ks * 16 + a_col) * 2));
#pragma unroll
      for (int p = 0; p < 2; p++)
        ldm_x4(bf[p], Bb + (uint32_t)(((b_row + p * 16) * kSmStrideH +
                                       ks * 16 + b_col) * 2));
#pragma unroll
      for (int mt = 0; mt < 4; mt++)
#pragma unroll
        for (int nt = 0; nt < 4; nt++)
          mma_f16(acc[mt][nt], af[mt], &bf[nt >> 1][(nt & 1) * 2]);
    }
  }

  // ---- epilogue ----
  const int mrow = lane >> 2;
  const int ncol = (lane & 3) * 2;
#pragma unroll
  for (int mt = 0; mt < 4; mt++) {
#pragma unroll
    for (int half_ = 0; half_ < 2; half_++) {
      int m = m0 + wm + mt * 16 + mrow + half_ * 8;
      if (m >= M) continue;
#pragma unroll
      for (int nt = 0; nt < 4; nt++) {
        int n = n0 + wn + nt * 8 + ncol;
        float v0 = acc[mt][nt][half_ * 2 + 0];
        float v1 = acc[mt][nt][half_ * 2 + 1];
        if (MODE == 0) {
          float bias0 = (n < kDim) ? b0[n] : ((n < 2 * kDim) ? 0.f : b1[n - 2 * kDim]);
          float bias1 = (n + 1 < kDim) ? b0[n + 1]
                        : ((n + 1 < 2 * kDim) ? 0.f : b1[n + 1 - 2 * kDim]);
          v0 += bias0; v1 += bias1;
          if (n < kDim) { v0 *= kScale; v1 *= kScale; }
          __half* C = (__half*)Cv;
          *(__half2*)(C + (size_t)m * N + n) = __floats2half2_rn(v0, v1);
        } else {
          float* C = (float*)Cv;
          v0 += b0[n]; v1 += b0[n + 1];
          *(float2*)(C + (size_t)m * N + n) = make_float2(v0, v1);
        }
      }
    }
  }
}

// ---------------------------------------------------------------------------
// FP16 tensor-core attention, TQ=64 query rows per block, 8 warps, 2 CTAs/SM.
// Phase A: S[64x256] = Q @ K^T   (warp tile 16x64; warps 4(M) x 2(N))
// Phase B: fp32 softmax(S + rpb); probs written fp16 OVERLAID on S rows
//          (row-private: scores read to regs before prob writes; Ph stride
//          520 halfs = 65x16B, odd multiple -> ldmatrix conflict-free)
// Phase C: O[64x64] = P @ V      (warp tile 16x32; V via ldmatrix.trans)
// K/V in 2 ping-pong cp.async buffers exactly as R15.
// ---------------------------------------------------------------------------
namespace {
constexpr int TQ    = 64;
constexpr int KC    = 128;
constexpr int SSTR  = 260;        // S (float) row stride
constexpr int PSTRH = SSTR * 2;   // 520 halfs — Ph overlays S rows
constexpr int QSTRH = 72;
constexpr int KVSTR = 72;         // K/V row stride (halfs)
constexpr int kOffQs = TQ * SSTR * 4;                 // 66560
constexpr int kOffKV = kOffQs + TQ * QSTRH * 2;       // +9216 = 75776
constexpr int kKVBuf = KC * KVSTR * 2;                // 18432 per buffer
constexpr int kAttnSmemBytes = kOffKV + 2 * kKVBuf;   // 112640
}  // namespace

__global__ __launch_bounds__(256, 2)
void attn_kernel() {
  extern __shared__ __align__(16) unsigned char smraw[];
  float*  S  = (float*)smraw;
  __half* Ph = (__half*)smraw;              // overlay on S (row-private)
  __half* Qs = (__half*)(smraw + kOffQs);

  const int t    = threadIdx.x;
  const int lane = t & 31;
  const int w    = t >> 5;
  const int tile = blockIdx.x;
  const int bh   = blockIdx.y;
  const int b    = bh / kHeads;
  const int h    = bh - b * kHeads;
  const int i0g  = tile * TQ;

  const __half* Qb = g_qkv + (size_t)b * kTok * kQkvN + h * 64;
  const __half* Kb = Qb + kDim;
  const __half* Vb = Qb + 2 * kDim;

  const uint32_t uS   = (uint32_t)__cvta_generic_to_shared(smraw);
  const uint32_t uQs  = uS + kOffQs;
  const uint32_t uKV0 = uS + kOffKV;
  const uint32_t uKV1 = uKV0 + kKVBuf;

  const int l7   = lane & 7;
  const int wq   = (w >> 1) * 16;          // query-row base for this warp
  const int wn64 = (w & 1) * 64;           // key base within 128-chunk (Phase A)
  const int a_row = wq + l7 + ((lane >> 3) & 1) * 8;
  const int a_col = ((lane >> 4) & 1) * 8;
  const int b_rowoff = ((lane >> 4) & 1) * 8 + l7;   // non-trans (K phase)
  const int b_col    = ((lane >> 3) & 1) * 8;
  const int vb_row = ((lane >> 3) & 1) * 8 + l7;     // trans (V phase): k rows
  const int vb_col = ((lane >> 4) & 1) * 8;          // trans: d cols
  const int lm = lane >> 2;
  const int lk = lane & 3;

  // KV chunk loader: 128 rows x 64 halfs via cp.async (zero-fill past kTok)
  auto load_kv = [&](const __half* src, uint32_t dstbase, int c0) {
#pragma unroll
    for (int i = 0; i < 4; i++) {
      int idx = t + i * 256;
      int row = idx >> 3;        // 0..127
      int j   = idx & 7;         // 16B chunk
      int gr  = c0 + row;
      int gc  = (gr < kTok) ? gr : (kTok - 1);   // clamp addr; zfill via pred
      cp_async16(dstbase + (uint32_t)(row * KVSTR * 2 + j * 16),
                 src + (size_t)gc * kQkvN + j * 8, gr < kTok);
    }
    cp_commit();
  };

  // ---- issue K0, K1; stage Q (64 rows x 64 halfs = 512 uint4, 2/thread) ----
  load_kv(Kb, uKV0, 0);      // group 1
  load_kv(Kb, uKV1, KC);     // group 2
#pragma unroll
  for (int p = 0; p < 2; p++) {
    int idx = t + p * 256;
    int i  = idx >> 3;
    int d0 = (idx & 7) * 8;
    int qi = i0g + i;
    uint4 v = {0u, 0u, 0u, 0u};
    if (qi < kTok) v = *(const uint4*)(Qb + (size_t)qi * kQkvN + d0);
    *(uint4*)&Qs[i * QSTRH + d0] = v;
  }
  __syncthreads();

  uint32_t aq[4][4];
#pragma unroll
  for (int ks = 0; ks < 4; ks++)
    ldm_x4(aq[ks], uQs + (uint32_t)((a_row * QSTRH + ks * 16 + a_col) * 2));

  // ---- Phase A: S = Q @ K^T (2 chunks, prefetched) ----
#pragma unroll
  for (int c0i = 0; c0i < 2; c0i++) {
    const int j0 = c0i * KC;
    const uint32_t uK = c0i ? uKV1 : uKV0;
    cp_wait1();
    __syncthreads();

    float acc[8][4] = {};
#pragma unroll
    for (int ks = 0; ks < 4; ks++) {
      uint32_t bf[4][4];
#pragma unroll
      for (int p = 0; p < 4; p++) {
        int nb = wn64 + p * 16;
        ldm_x4(bf[p], uK + (uint32_t)(((nb + b_rowoff) * KVSTR +
                                       ks * 16 + b_col) * 2));
      }
#pragma unroll
      for (int nt = 0; nt < 8; nt++)
        mma_f16(acc[nt], aq[ks], &bf[nt >> 1][(nt & 1) * 2]);
    }
#pragma unroll
    for (int nt = 0; nt < 8; nt++) {
      int col = j0 + wn64 + nt * 8 + lk * 2;
      int r   = wq + lm;
      *(float2*)&S[r * SSTR + col]       = make_float2(acc[nt][0], acc[nt][1]);
      *(float2*)&S[(r + 8) * SSTR + col] = make_float2(acc[nt][2], acc[nt][3]);
    }
    __syncthreads();                 // all warps done with this K buffer
    load_kv(Vb, uK, j0);             // overwrite with V chunk (groups 3, 4)
  }

  // ---- Phase B: softmax(S + rpb) in fp32; probs fp16 overlaid on S ----
  // (V0/V1 loads in flight underneath). 8 rows per warp; row-private overlay.
  {
#pragma unroll
    for (int r = 0; r < 8; r++) {
      int i  = w * 8 + r;
      int qi = min(i0g + i, kTok - 1);
      const float* rp = g_rpb + ((size_t)h * kTok + qi) * kTok;
      float vals[8];
      float mx = -1e30f;
#pragma unroll
      for (int k = 0; k < 8; k++) {
        int j = lane + k * 32;
        float v = -1e30f;
        if (j < kTok) v = S[i * SSTR + j] + rp[j];
        vals[k] = v;
        mx = fmaxf(mx, v);
      }
#pragma unroll
      for (int o = 16; o; o >>= 1) mx = fmaxf(mx, __shfl_xor_sync(0xffffffffu, mx, o));
      float sum = 0.f;
#pragma unroll
      for (int k = 0; k < 8; k++) {
        int j = lane + k * 32;
        float e = (j < kTok) ? __expf(vals[k] - mx) : 0.f;
        vals[k] = e;
        sum += e;
      }
#pragma unroll
      for (int o = 16; o; o >>= 1) sum += __shfl_xor_sync(0xffffffffu, sum, o);
      float inv = 1.f / sum;
#pragma unroll
      for (int k = 0; k < 8; k++) {
        int j = lane + k * 32;
        Ph[i * PSTRH + j] = __float2half_rn((j < kTok) ? vals[k] * inv : 0.f);
      }
    }
  }

  // ---- Phase C: O = P @ V (V row-major; B-fragment via ldmatrix.trans) ----
  float accO[4][4] = {};
  const int dbase = (w & 1) * 32;    // d base for this warp (Phase C N = 32)
#pragma unroll
  for (int c0i = 0; c0i < 2; c0i++) {
    const int j0 = c0i * KC;
    const uint32_t uV = c0i ? uKV1 : uKV0;
    if (c0i == 0) cp_wait1(); else cp_wait0();
    __syncthreads();   // Ph visible (c0i==0) + all threads' V parts landed

#pragma unroll
    for (int ks = 0; ks < 8; ks++) {
      uint32_t ap[4];
      ldm_x4(ap, uS + (uint32_t)((a_row * PSTRH + j0 + ks * 16 + a_col) * 2));
#pragma unroll
      for (int p = 0; p < 2; p++) {
        uint32_t bv[4];
        int nb = dbase + p * 16;
        ldm_x4_t(bv, uV + (uint32_t)(((ks * 16 + vb_row) * KVSTR +
                                      nb + vb_col) * 2));
#pragma unroll
        for (int q = 0; q < 2; q++)
          mma_f16(accO[p * 2 + q], ap, &bv[q * 2]);
      }
    }
  }

  // ---- epilogue: write g_attn (fp16) ----
#pragma unroll
  for (int nt = 0; nt < 4; nt++) {
    int dcol = dbase + nt * 8 + lk * 2;
#pragma unroll
    for (int half_ = 0; half_ < 2; half_++) {
      int i = i0g + wq + lm + half_ * 8;
      if (i < kTok) {
        __half2 hv = __floats2half2_rn(accO[nt][half_ * 2 + 0],
                                       accO[nt][half_ * 2 + 1]);
        *(__half2*)(g_attn + ((size_t)b * kTok + i) * kDim + h * 64 + dcol) = hv;
      }
    }
  }
}

// ---------------------------------------------------------------------------
// Launch
// ---------------------------------------------------------------------------
extern "C" void kernel_launch(void* const* d_in, const int* in_sizes, int n_in,
                              void* d_out, int out_size) {
  const float* x         = (const float*)d_in[0];
  const float* qkv_w     = (const float*)d_in[1];
  const float* q_bias    = (const float*)d_in[2];
  const float* v_bias    = (const float*)d_in[3];
  const float* rpb_table = (const float*)d_in[4];
  const float* proj_w    = (const float*)d_in[5];
  const float* proj_b    = (const float*)d_in[6];
  const int*   rel_idx   = (const int*)d_in[7];
  float* out = (float*)d_out;

  __half *qkv_ptr, *attn_ptr, *x_ptr, *wqkv_ptr, *wproj_ptr;
  cudaGetSymbolAddress((void**)&qkv_ptr, g_qkv);
  cudaGetSymbolAddress((void**)&attn_ptr, g_attn);
  cudaGetSymbolAddress((void**)&x_ptr, g_x);
  cudaGetSymbolAddress((void**)&wqkv_ptr, g_wqkv);
  cudaGetSymbolAddress((void**)&wproj_ptr, g_wproj);

  // (0) fused fp32 -> fp16 conversion of all GEMM inputs
  f2h_fused<<<(kN4Total + 255) / 256, 256>>>(x, qkv_w, proj_w);

  // (1) relative position bias expansion
  rpb_expand<<<(kTok * kTok + 255) / 256, 256>>>(rel_idx, rpb_table);

  // (2) QKV projection (fp16 in, fp16 out with bias + q-scale)
  cudaFuncSetAttribute(gemm_f16<0>, cudaFuncAttributeMaxDynamicSharedMemorySize,
                       kGemmSmemBytes);
  {
    dim3 grid(kQkvN / 128, (kM + 127) / 128);
    gemm_f16<0><<<grid, 256, kGemmSmemBytes>>>(x_ptr, wqkv_ptr, qkv_ptr,
                                               kM, kDim, kQkvN, q_bias, v_bias);
  }

  // (3) fp16 tensor-core attention (TQ=64, pipelined K/V, S/Ph overlay)
  cudaFuncSetAttribute(attn_kernel, cudaFuncAttributeMaxDynamicSharedMemorySize,
                       kAttnSmemBytes);
  attn_kernel<<<dim3((kTok + TQ - 1) / TQ, kBatch * kHeads), 256,
                kAttnSmemBytes>>>();

  // (4) output projection (fp16 in, fp32 out with bias)
  cudaFuncSetAttribute(gemm_f16<1>, cudaFuncAttributeMaxDynamicSharedMemorySize,
                       kGemmSmemBytes);
  {
    dim3 grid(kDim / 128, (kM + 127) / 128);
    gemm_f16<1><<<grid, 256, kGemmSmemBytes>>>(attn_ptr, wproj_ptr, out,
                                               kM, kDim, kDim, proj_b, nullptr);
  }
}